// round 4
// baseline (speedup 1.0000x reference)
#include <cuda_runtime.h>
#include <cuda_bf16.h>

// M=64, G=48, N=4096, GRID_RANGE=2.0
// Inputs: 0:x(N) 1:y(N) 2:z(N) 3:mu_x(M*G) 4:mu_y(M*G) 5:mu_z(M*G)
//         6:sigmas(M*G*3) 7:r(M*G*4) 8:weight(M*G)
// Output: float (N, M) row-major.

#define MDIM 64
#define GDIM 48

__device__ __forceinline__ float fast_exp2(float q) {
    float p; asm("ex2.approx.ftz.f32 %0, %1;" : "=f"(p) : "f"(q)); return p;
}

// One m per block (blockIdx.y), 128 points per block (1/thread), grid.x = 32.
//
// Math: pdf = exp2( a_g*|p|^2-ish quad + b_g.p + c_g ), out = sum_g w_g*pdf.
// Iso fast path (detected block-uniformly from raw inputs: identity-axis
// quaternion + equal sigmas + sigma uniform across g): A = a*I with a common
// to all g, so exp2(a*s2) is factored out of the g-sum entirely:
//   out = exp2(a*s2) * sum_g w_g * exp2(b_g.p + c_g)
// -> 3 FMA + 1 MUFU + 1 acc FMA per (g,point) eval.
__global__ __launch_bounds__(128) void gauss_fused_kernel(
    const float* __restrict__ xs, const float* __restrict__ ys,
    const float* __restrict__ zs,
    const float* __restrict__ mu_x, const float* __restrict__ mu_y,
    const float* __restrict__ mu_z, const float* __restrict__ sigmas,
    const float* __restrict__ rq, const float* __restrict__ weight,
    float* __restrict__ out, int N) {
    __shared__ __align__(16) float4 sB[GDIM];     // iso: {b0,b1,b2,c}
    __shared__ float sw[GDIM];                    // iso: w
    __shared__ float s_a;                         // iso: common a
    __shared__ __align__(16) float4 sg[GDIM * 3]; // generic coeffs

    const int m = blockIdx.y;
    const int t = threadIdx.x;

    // ---- cheap block-uniform iso detection from raw inputs ----
    int pred = 1;
    float qx = 0.f, qy = 0.f, qz = 0.f, qw = 1.f;
    float s0 = 0.f, s1 = 0.f, s2c = 0.f;
    if (t < GDIM) {
        const int idx = m * GDIM + t;
        qw = rq[idx * 4 + 0];
        qx = rq[idx * 4 + 1];
        qy = rq[idx * 4 + 2];
        qz = rq[idx * 4 + 3];
        s0 = sigmas[idx * 3 + 0];
        s1 = sigmas[idx * 3 + 1];
        s2c = sigmas[idx * 3 + 2];
        const float s_g0 = sigmas[(m * GDIM) * 3];   // g=0's sigma (broadcast)
        pred = (qx == 0.f) & (qy == 0.f) & (qz == 0.f) &
               (s0 == s1) & (s0 == s2c) & (s0 == s_g0);
    }
    const int iso = __syncthreads_and(pred);

    const float kk = -0.72134752044448169f;  // -0.5 * log2(e)

    // ---- prologue: build this m's 48 coefficient sets ----
    if (t < GDIM) {
        const int idx = m * GDIM + t;
        const float m0 = mu_x[idx], m1 = mu_y[idx], m2 = mu_z[idx];
        const float w = weight[idx];
        if (iso) {
            const float a = kk / (s0 * s0);
            const float b0 = -2.f * (a * m0);
            const float b1 = -2.f * (a * m1);
            const float b2 = -2.f * (a * m2);
            const float c = a * m0 * m0 + a * m1 * m1 + a * m2 * m2;
            sB[t] = make_float4(b0, b1, b2, c);
            sw[t] = w;
            if (t == 0) s_a = a;
        } else {
            float inv = rsqrtf(qw * qw + qx * qx + qy * qy + qz * qz);
            float nw = qw * inv, nx = qx * inv, ny = qy * inv, nz = qz * inv;
            float R[3][3];
            R[0][0] = 1.f - 2.f * (ny * ny + nz * nz);
            R[0][1] = 2.f * (nx * ny - nw * nz);
            R[0][2] = 2.f * (nx * nz + nw * ny);
            R[1][0] = 2.f * (nx * ny + nw * nz);
            R[1][1] = 1.f - 2.f * (nx * nx + nz * nz);
            R[1][2] = 2.f * (ny * nz - nw * nx);
            R[2][0] = 2.f * (nx * nz - nw * ny);
            R[2][1] = 2.f * (ny * nz + nw * nx);
            R[2][2] = 1.f - 2.f * (nx * nx + ny * ny);
            float is0 = 1.f / (s0 * s0);
            float is1 = 1.f / (s1 * s1);
            float is2 = 1.f / (s2c * s2c);
            float A[3][3];
            #pragma unroll
            for (int i = 0; i < 3; ++i)
                #pragma unroll
                for (int j = 0; j < 3; ++j)
                    A[i][j] = kk * (R[i][0] * R[j][0] * is0 +
                                    R[i][1] * R[j][1] * is1 +
                                    R[i][2] * R[j][2] * is2);
            float b0 = -2.f * (A[0][0] * m0 + A[0][1] * m1 + A[0][2] * m2);
            float b1 = -2.f * (A[1][0] * m0 + A[1][1] * m1 + A[1][2] * m2);
            float b2 = -2.f * (A[2][0] * m0 + A[2][1] * m1 + A[2][2] * m2);
            float c  = A[0][0] * m0 * m0 + A[1][1] * m1 * m1 + A[2][2] * m2 * m2
                     + 2.f * (A[0][1] * m0 * m1 + A[0][2] * m0 * m2 + A[1][2] * m1 * m2);
            sg[t * 3 + 0] = make_float4(A[0][0], A[1][1], A[2][2], 2.f * A[0][1]);
            sg[t * 3 + 1] = make_float4(2.f * A[0][2], 2.f * A[1][2], b0, b1);
            sg[t * 3 + 2] = make_float4(b2, c, w, 0.f);
        }
    }
    __syncthreads();

    // ---- main loop: 1 point per thread ----
    const int n = blockIdx.x * 128 + t;
    float x = 0.f, y = 0.f, z = 0.f;
    if (n < N) {
        x = xs[n];
        y = ys[n] + 1.f;   // (y+1)/2 * GRID_RANGE with GRID_RANGE=2
        z = zs[n] + 1.f;
    }

    float result;
    if (iso) {
        const float s2 = fmaf(z, z, fmaf(y, y, x * x));
        const float E = fast_exp2(s_a * s2);
        float acc = 0.f;
        #pragma unroll
        for (int g = 0; g < GDIM; ++g) {
            const float4 B = sB[g];
            const float q = fmaf(B.x, x, fmaf(B.y, y, fmaf(B.z, z, B.w)));
            acc = fmaf(sw[g], fast_exp2(q), acc);
        }
        result = E * acc;
    } else {
        const float xx = x * x, yy = y * y, zz = z * z;
        const float xy = x * y, xz = x * z, yz = y * z;
        float acc = 0.f;
        #pragma unroll
        for (int g = 0; g < GDIM; ++g) {
            const float4 cA = sg[g * 3 + 0];
            const float4 cB = sg[g * 3 + 1];
            const float4 cC = sg[g * 3 + 2];
            float q = cC.y;
            q = fmaf(cA.x, xx, q);
            q = fmaf(cA.y, yy, q);
            q = fmaf(cA.z, zz, q);
            q = fmaf(cA.w, xy, q);
            q = fmaf(cB.x, xz, q);
            q = fmaf(cB.y, yz, q);
            q = fmaf(cB.z, x, q);
            q = fmaf(cB.w, y, q);
            q = fmaf(cC.x, z, q);
            acc = fmaf(cC.z, fast_exp2(q), acc);
        }
        result = acc;
    }

    if (n < N) out[n * MDIM + m] = result;
}

extern "C" void kernel_launch(void* const* d_in, const int* in_sizes, int n_in,
                              void* d_out, int out_size) {
    const float* x      = (const float*)d_in[0];
    const float* y      = (const float*)d_in[1];
    const float* z      = (const float*)d_in[2];
    const float* mu_x   = (const float*)d_in[3];
    const float* mu_y   = (const float*)d_in[4];
    const float* mu_z   = (const float*)d_in[5];
    const float* sigmas = (const float*)d_in[6];
    const float* r      = (const float*)d_in[7];
    const float* weight = (const float*)d_in[8];
    float* out = (float*)d_out;

    const int N = in_sizes[0];

    dim3 grid((N + 127) / 128, MDIM);
    gauss_fused_kernel<<<grid, 128>>>(x, y, z, mu_x, mu_y, mu_z,
                                      sigmas, r, weight, out, N);
}

// round 5
// speedup vs baseline: 1.1625x; 1.1625x over previous
#include <cuda_runtime.h>
#include <cuda_bf16.h>

// M=64, G=48, N=4096, GRID_RANGE=2.0
// Inputs: 0:x(N) 1:y(N) 2:z(N) 3:mu_x(M*G) 4:mu_y(M*G) 5:mu_z(M*G)
//         6:sigmas(M*G*3) 7:r(M*G*4) 8:weight(M*G)
// Output: float (N, M) row-major.

#define MDIM 64
#define GDIM 48

__device__ __forceinline__ float fast_exp2(float q) {
    float p; asm("ex2.approx.ftz.f32 %0, %1;" : "=f"(p) : "f"(q)); return p;
}

// One m per block (blockIdx.y), 256 points per block (1/thread), grid.x = 16.
//
// pdf = exp2( p^T A p + b.p + c ), out = sum_g w * pdf, A = -0.5*log2(e)*R S^-2 R^T.
// Iso fast path (identity-axis quaternion, equal sigmas, uniform across g):
// A = a*I with a common to all g, so
//   out = exp2(a*|p|^2) * sum_g (w_g * exp2(c_g)) * exp2(b_g . p)
// -> per (g,point): 1 LDS.128 {b0,b1,b2,w'}, 3 FMA, 1 MUFU, 1 acc FMA.
__global__ __launch_bounds__(256) void gauss_fused_kernel(
    const float* __restrict__ xs, const float* __restrict__ ys,
    const float* __restrict__ zs,
    const float* __restrict__ mu_x, const float* __restrict__ mu_y,
    const float* __restrict__ mu_z, const float* __restrict__ sigmas,
    const float* __restrict__ rq, const float* __restrict__ weight,
    float* __restrict__ out, int N) {
    __shared__ __align__(16) float4 sB[GDIM];      // iso: {b0,b1,b2,w*exp2(c)}
    __shared__ float s_a;                          // iso: common a
    __shared__ __align__(16) float4 sg[GDIM * 3];  // generic coeffs

    const int m = blockIdx.y;
    const int t = threadIdx.x;
    const int n = blockIdx.x * 256 + t;

    // ---- early point loads (independent of everything below) ----
    float x = 0.f, y = 0.f, z = 0.f;
    if (n < N) {
        x = xs[n];
        y = ys[n] + 1.f;   // (y+1)/2 * GRID_RANGE with GRID_RANGE=2
        z = zs[n] + 1.f;
    }

    // ---- prologue: build BOTH coefficient variants, detect iso ----
    int pred = 1;
    if (t < GDIM) {
        const int idx = m * GDIM + t;
        const float4 q4 = reinterpret_cast<const float4*>(rq)[idx];  // w,x,y,z
        const float s0  = sigmas[idx * 3 + 0];
        const float s1  = sigmas[idx * 3 + 1];
        const float s2c = sigmas[idx * 3 + 2];
        const float sg0 = sigmas[(m * GDIM) * 3];
        const float m0 = mu_x[idx], m1 = mu_y[idx], m2 = mu_z[idx];
        const float w = weight[idx];

        pred = (q4.y == 0.f) & (q4.z == 0.f) & (q4.w == 0.f) &
               (s0 == s1) & (s0 == s2c) & (s0 == sg0);

        const float inv = rsqrtf(q4.x * q4.x + q4.y * q4.y + q4.z * q4.z + q4.w * q4.w);
        const float nw = q4.x * inv, nx = q4.y * inv, ny = q4.z * inv, nz = q4.w * inv;
        float R[3][3];
        R[0][0] = 1.f - 2.f * (ny * ny + nz * nz);
        R[0][1] = 2.f * (nx * ny - nw * nz);
        R[0][2] = 2.f * (nx * nz + nw * ny);
        R[1][0] = 2.f * (nx * ny + nw * nz);
        R[1][1] = 1.f - 2.f * (nx * nx + nz * nz);
        R[1][2] = 2.f * (ny * nz - nw * nx);
        R[2][0] = 2.f * (nx * nz - nw * ny);
        R[2][1] = 2.f * (ny * nz + nw * nx);
        R[2][2] = 1.f - 2.f * (nx * nx + ny * ny);

        const float is0 = 1.f / (s0 * s0);
        const float is1 = 1.f / (s1 * s1);
        const float is2 = 1.f / (s2c * s2c);

        const float kk = -0.72134752044448169f;  // -0.5 * log2(e)
        float A[3][3];
        #pragma unroll
        for (int i = 0; i < 3; ++i)
            #pragma unroll
            for (int j = 0; j < 3; ++j)
                A[i][j] = kk * (R[i][0] * R[j][0] * is0 +
                                R[i][1] * R[j][1] * is1 +
                                R[i][2] * R[j][2] * is2);

        const float b0 = -2.f * (A[0][0] * m0 + A[0][1] * m1 + A[0][2] * m2);
        const float b1 = -2.f * (A[1][0] * m0 + A[1][1] * m1 + A[1][2] * m2);
        const float b2 = -2.f * (A[2][0] * m0 + A[2][1] * m1 + A[2][2] * m2);
        const float c  = A[0][0] * m0 * m0 + A[1][1] * m1 * m1 + A[2][2] * m2 * m2
                 + 2.f * (A[0][1] * m0 * m1 + A[0][2] * m0 * m2 + A[1][2] * m1 * m2);

        sg[t * 3 + 0] = make_float4(A[0][0], A[1][1], A[2][2], 2.f * A[0][1]);
        sg[t * 3 + 1] = make_float4(2.f * A[0][2], 2.f * A[1][2], b0, b1);
        sg[t * 3 + 2] = make_float4(b2, c, w, 0.f);

        // iso variant (valid exactly when pred holds block-wide)
        sB[t] = make_float4(b0, b1, b2, w * fast_exp2(c));
        if (t == 0) s_a = A[0][0];
    }
    const int iso = __syncthreads_and(pred);   // single barrier + reduction

    // ---- main loop ----
    float result;
    if (iso) {
        const float s2 = fmaf(z, z, fmaf(y, y, x * x));
        const float E = fast_exp2(s_a * s2);
        float acc0 = 0.f, acc1 = 0.f;
        #pragma unroll
        for (int g = 0; g < GDIM; g += 2) {
            const float4 B0 = sB[g];
            const float4 B1 = sB[g + 1];
            const float qa = fmaf(B0.x, x, fmaf(B0.y, y, B0.z * z));
            const float qb = fmaf(B1.x, x, fmaf(B1.y, y, B1.z * z));
            acc0 = fmaf(B0.w, fast_exp2(qa), acc0);
            acc1 = fmaf(B1.w, fast_exp2(qb), acc1);
        }
        result = E * (acc0 + acc1);
    } else {
        const float xx = x * x, yy = y * y, zz = z * z;
        const float xy = x * y, xz = x * z, yz = y * z;
        float acc = 0.f;
        #pragma unroll
        for (int g = 0; g < GDIM; ++g) {
            const float4 cA = sg[g * 3 + 0];
            const float4 cB = sg[g * 3 + 1];
            const float4 cC = sg[g * 3 + 2];
            float q = cC.y;
            q = fmaf(cA.x, xx, q);
            q = fmaf(cA.y, yy, q);
            q = fmaf(cA.z, zz, q);
            q = fmaf(cA.w, xy, q);
            q = fmaf(cB.x, xz, q);
            q = fmaf(cB.y, yz, q);
            q = fmaf(cB.z, x, q);
            q = fmaf(cB.w, y, q);
            q = fmaf(cC.x, z, q);
            acc = fmaf(cC.z, fast_exp2(q), acc);
        }
        result = acc;
    }

    if (n < N) out[n * MDIM + m] = result;
}

extern "C" void kernel_launch(void* const* d_in, const int* in_sizes, int n_in,
                              void* d_out, int out_size) {
    const float* x      = (const float*)d_in[0];
    const float* y      = (const float*)d_in[1];
    const float* z      = (const float*)d_in[2];
    const float* mu_x   = (const float*)d_in[3];
    const float* mu_y   = (const float*)d_in[4];
    const float* mu_z   = (const float*)d_in[5];
    const float* sigmas = (const float*)d_in[6];
    const float* r      = (const float*)d_in[7];
    const float* weight = (const float*)d_in[8];
    float* out = (float*)d_out;

    const int N = in_sizes[0];

    dim3 grid((N + 255) / 256, MDIM);
    gauss_fused_kernel<<<grid, 256>>>(x, y, z, mu_x, mu_y, mu_z,
                                      sigmas, r, weight, out, N);
}